// round 10
// baseline (speedup 1.0000x reference)
#include <cuda_runtime.h>
#include <cuda_bf16.h>
#include <cstdint>
#include <string.h>
#include <math.h>

typedef __nv_bfloat16 bf16;

#define B_ 8
#define C_ 512
#define N_ 2048
#define CH_ 256

// ---- device-global scratch ----
__device__ bf16  g_xt [B_ * N_ * C_];             // [n][c] bf16
__device__ bf16  g_Wqk[2 * CH_ * C_];             // rows 0-255 Wq, 256-511 Wk
__device__ bf16  g_Wv [C_ * C_];
__device__ float g_bqk[2 * CH_];                  // packed bq|bk
__device__ bf16  g_QK [B_ * N_ * C_];             // [n][0..255]=Q, [256..511]=K
__device__ bf16  g_V  [B_ * C_ * N_];             // [c][m]
__device__ bf16  g_S  [(size_t)B_ * N_ * N_];     // [n][m] unscaled logits, bf16
__device__ bf16  g_P  [(size_t)B_ * N_ * N_];     // [n][m] probs, bf16

// ===========================================================================
// PTX helpers
// ===========================================================================
__device__ __forceinline__ uint32_t smem_u32(const void* p) {
    uint32_t a;
    asm("{ .reg .u64 t; cvta.to.shared.u64 t, %1; cvt.u32.u64 %0, t; }"
        : "=r"(a) : "l"(p));
    return a;
}
__device__ __forceinline__ void cp_async16(uint32_t dst, const void* src) {
    asm volatile("cp.async.cg.shared.global [%0], [%1], 16;\n" :: "r"(dst), "l"(src));
}
__device__ __forceinline__ void cp_commit() {
    asm volatile("cp.async.commit_group;\n");
}
template<int NW> __device__ __forceinline__ void cp_wait() {
    asm volatile("cp.async.wait_group %0;\n" :: "n"(NW));
}
__device__ __forceinline__ void ldsm4(uint32_t* r, uint32_t addr) {
    asm volatile("ldmatrix.sync.aligned.m8n8.x4.shared.b16 {%0,%1,%2,%3}, [%4];\n"
                 : "=r"(r[0]), "=r"(r[1]), "=r"(r[2]), "=r"(r[3]) : "r"(addr));
}
__device__ __forceinline__ void mma16816(float* c, const uint32_t* a,
                                         uint32_t b0, uint32_t b1) {
    asm volatile(
        "mma.sync.aligned.m16n8k16.row.col.f32.bf16.bf16.f32 "
        "{%0,%1,%2,%3}, {%4,%5,%6,%7}, {%8,%9}, {%0,%1,%2,%3};\n"
        : "+f"(c[0]), "+f"(c[1]), "+f"(c[2]), "+f"(c[3])
        : "r"(a[0]), "r"(a[1]), "r"(a[2]), "r"(a[3]), "r"(b0), "r"(b1));
}
__device__ __forceinline__ uint32_t pack_bf16x2(float lo, float hi) {
    __nv_bfloat162 h = __float22bfloat162_rn(make_float2(lo, hi));
    uint32_t u;
    memcpy(&u, &h, 4);
    return u;
}
__device__ __forceinline__ float2 unpack_bf16x2(uint32_t u) {
    __nv_bfloat162 h;
    memcpy(&h, &u, 4);
    return __bfloat1622float2(h);
}

// ===========================================================================
// K-major SS GEMM: D[i,j] = sum_k A[i,k]*B[j,k] + epilogue
// CTA tile 256x128, 256 threads (8 warps, 4x2 grid of 64x64 warp tiles),
// K-chunks of 64, 3-stage cp.async pipeline, XOR-swizzled smem (128B rows).
// Stage layout: A 256x64 (32KB) | B 128x64 (16KB)  -> 48KB/stage, 144KB total.
//   MODE 1: bf16 out + bias[j]
//   MODE 2: bf16 out + bias[i]
//   MODE 3: fp32 out + res[i][j]
//   MODE 4: bf16 out (plain)
// Requires rows%256==0, cols%128==0, Ktot%64==0.
// ===========================================================================
#define NSTG 3
#define STGB 49152
#define SMEMB (NSTG * STGB)

template<int MODE>
__global__ void __launch_bounds__(256, 1)
mma_gemm(const bf16* __restrict__ Ag, const bf16* __restrict__ Bg,
         const float* __restrict__ bias, const float* __restrict__ res,
         void* __restrict__ Dg, int Ktot, int lda, int ldb, int ldd,
         size_t sA, size_t sB, size_t sD, size_t sRes)
{
    extern __shared__ char smem[];
    const uint32_t s0 = smem_u32(smem);

    const int tid = threadIdx.x, warp = tid >> 5, lane = tid & 31;
    const int bz = blockIdx.z;
    const int i0 = blockIdx.y * 256, j0 = blockIdx.x * 128;
    const bf16* Ab = Ag + sA * bz;
    const bf16* Bb = Bg + sB * bz;

    const int wm = (warp >> 1) * 64;    // 0/64/128/192
    const int wn = (warp & 1) * 64;     // 0/64

    const int rAl = lane & 15;
    const int aHalf = lane >> 4;
    const int rBl = (lane & 7) + ((lane & 16) >> 1);
    const int bHalf = (lane >> 3) & 1;

    float acc[4][8][4];
    #pragma unroll
    for (int mi = 0; mi < 4; mi++)
        #pragma unroll
        for (int ni = 0; ni < 8; ni++)
            #pragma unroll
            for (int e = 0; e < 4; e++) acc[mi][ni][e] = 0.0f;

    auto load_stage = [&](int t) {
        const uint32_t base = s0 + (uint32_t)(t % NSTG) * (uint32_t)STGB;
        const int k0 = t * 64;
        #pragma unroll
        for (int it = 0; it < 12; it++) {
            int q = it * 256 + tid;                 // 0..3071
            if (q < 2048) {                          // A: 256 rows x 8 chunks
                int row = q >> 3, c = q & 7;
                uint32_t dst = base
                             + (uint32_t)(row * 128 + ((c ^ (row & 7)) << 4));
                cp_async16(dst, Ab + (size_t)(i0 + row) * lda + k0 + c * 8);
            } else {                                 // B: 128 rows x 8 chunks
                int qb = q - 2048;
                int row = qb >> 3, c = qb & 7;
                uint32_t dst = base + 32768u
                             + (uint32_t)(row * 128 + ((c ^ (row & 7)) << 4));
                cp_async16(dst, Bb + (size_t)(j0 + row) * ldb + k0 + c * 8);
            }
        }
        cp_commit();
    };

    const int T = Ktot >> 6;
    load_stage(0);
    if (T > 1) load_stage(1); else cp_commit();

    for (int t = 0; t < T; t++) {
        if (t + 2 < T) load_stage(t + 2); else cp_commit();
        cp_wait<2>();
        __syncthreads();

        const uint32_t sa = s0 + (uint32_t)(t % NSTG) * (uint32_t)STGB;
        const uint32_t sb = sa + 32768u;
        #pragma unroll
        for (int k16 = 0; k16 < 4; k16++) {
            uint32_t a[4][4], b[4][4];
            #pragma unroll
            for (int mi = 0; mi < 4; mi++) {
                int row = wm + mi * 16 + rAl;
                int ch = 2 * k16 + aHalf;
                ldsm4(a[mi], sa + (uint32_t)(row * 128 + ((ch ^ (row & 7)) << 4)));
            }
            #pragma unroll
            for (int nh = 0; nh < 4; nh++) {
                int row = wn + nh * 16 + rBl;
                int ch = 2 * k16 + bHalf;
                ldsm4(b[nh], sb + (uint32_t)(row * 128 + ((ch ^ (row & 7)) << 4)));
            }
            #pragma unroll
            for (int mi = 0; mi < 4; mi++)
                #pragma unroll
                for (int ni = 0; ni < 8; ni++)
                    mma16816(acc[mi][ni], a[mi],
                             b[ni >> 1][(ni & 1) * 2], b[ni >> 1][(ni & 1) * 2 + 1]);
        }
        __syncthreads();
    }

    // ---- Epilogue ----
    const int er = lane >> 2;
    const int ec = 2 * (lane & 3);
    #pragma unroll
    for (int mi = 0; mi < 4; mi++)
        #pragma unroll
        for (int ni = 0; ni < 8; ni++) {
            const float* a4 = acc[mi][ni];
            int gm = i0 + wm + mi * 16 + er;
            int gn = j0 + wn + ni * 8 + ec;
            if (MODE == 3) {
                float* D = (float*)Dg + sD * bz;
                const float* R = res + sRes * bz;
                float2 r0 = *(const float2*)&R[(size_t)gm * ldd + gn];
                float2 r1 = *(const float2*)&R[(size_t)(gm + 8) * ldd + gn];
                *(float2*)&D[(size_t)gm * ldd + gn] =
                    make_float2(r0.x + a4[0], r0.y + a4[1]);
                *(float2*)&D[(size_t)(gm + 8) * ldd + gn] =
                    make_float2(r1.x + a4[2], r1.y + a4[3]);
            } else if (MODE == 4) {
                bf16* D = (bf16*)Dg + sD * bz;
                *(__nv_bfloat162*)&D[(size_t)gm * ldd + gn] =
                    __float22bfloat162_rn(make_float2(a4[0], a4[1]));
                *(__nv_bfloat162*)&D[(size_t)(gm + 8) * ldd + gn] =
                    __float22bfloat162_rn(make_float2(a4[2], a4[3]));
            } else {
                bf16* D = (bf16*)Dg + sD * bz;
                float b0, b1, b2, b3;
                if (MODE == 1) {
                    b0 = bias[gn]; b1 = bias[gn + 1]; b2 = b0; b3 = b1;
                } else {
                    b0 = b1 = bias[gm]; b2 = b3 = bias[gm + 8];
                }
                *(__nv_bfloat162*)&D[(size_t)gm * ldd + gn] =
                    __float22bfloat162_rn(make_float2(a4[0] + b0, a4[1] + b1));
                *(__nv_bfloat162*)&D[(size_t)(gm + 8) * ldd + gn] =
                    __float22bfloat162_rn(make_float2(a4[2] + b2, a4[3] + b3));
            }
        }
}

// ===========================================================================
// Fused prep: weight conversions + bias pack + x transpose, one launch.
// ===========================================================================
__global__ void __launch_bounds__(256)
prep_all(const float* __restrict__ Wq, const float* __restrict__ Wk,
         const float* __restrict__ Wv, const float* __restrict__ bq,
         const float* __restrict__ bk, const float* __restrict__ x)
{
    __shared__ float tile[32][33];
    const int b = blockIdx.x;
    const int tid = threadIdx.x;

    if (b < 512) {
        const float4* src;
        __nv_bfloat162* dst;
        int idx;
        if (b < 128) {
            src = (const float4*)Wq; dst = (__nv_bfloat162*)g_Wqk;
            idx = b * 256 + tid;
        } else if (b < 256) {
            src = (const float4*)Wk; dst = (__nv_bfloat162*)(g_Wqk + CH_ * C_);
            idx = (b - 128) * 256 + tid;
        } else {
            src = (const float4*)Wv; dst = (__nv_bfloat162*)g_Wv;
            idx = (b - 256) * 256 + tid;
        }
        float4 v = src[idx];
        dst[2 * idx]     = __float22bfloat162_rn(make_float2(v.x, v.y));
        dst[2 * idx + 1] = __float22bfloat162_rn(make_float2(v.z, v.w));
        if (b >= 256) {
            int idx2 = idx + 256 * 128;
            float4 v2 = ((const float4*)Wv)[idx2];
            dst[2 * idx2]     = __float22bfloat162_rn(make_float2(v2.x, v2.y));
            dst[2 * idx2 + 1] = __float22bfloat162_rn(make_float2(v2.z, v2.w));
        }
    } else if (b == 512) {
        g_bqk[tid]        = bq[tid];
        g_bqk[tid + CH_]  = bk[tid];
    } else {
        int t = b - 513;
        int bx = t & 63;
        int by = (t >> 6) & 15;
        int bz = t >> 10;
        const int c0 = by * 32, n0 = bx * 32;
        const float* xb = x + (size_t)bz * C_ * N_;
        bf16* xtb = g_xt + (size_t)bz * N_ * C_;
        const int tx = tid & 31, ty = tid >> 5;
        #pragma unroll
        for (int i = 0; i < 4; i++)
            tile[ty + 8 * i][tx] = xb[(size_t)(c0 + ty + 8 * i) * N_ + n0 + tx];
        __syncthreads();
        #pragma unroll
        for (int i = 0; i < 4; i++)
            xtb[(size_t)(n0 + ty + 8 * i) * C_ + c0 + tx] =
                __float2bfloat16(tile[tx][ty + 8 * i]);
    }
}

// ===========================================================================
// Softmax over last dim (2048). bf16 in (x1/16 at load), bf16 out.
// ===========================================================================
__global__ void __launch_bounds__(256)
softmax_kernel(const bf16* __restrict__ S, bf16* __restrict__ P)
{
    const uint4* row = (const uint4*)(S + (size_t)blockIdx.x * N_);
    uint4* prow = (uint4*)(P + (size_t)blockIdx.x * N_);
    const int tid = threadIdx.x;

    uint4 u = row[tid];
    float v[8];
    {
        float2 f;
        f = unpack_bf16x2(u.x); v[0] = f.x * 0.0625f; v[1] = f.y * 0.0625f;
        f = unpack_bf16x2(u.y); v[2] = f.x * 0.0625f; v[3] = f.y * 0.0625f;
        f = unpack_bf16x2(u.z); v[4] = f.x * 0.0625f; v[5] = f.y * 0.0625f;
        f = unpack_bf16x2(u.w); v[6] = f.x * 0.0625f; v[7] = f.y * 0.0625f;
    }
    float mx = v[0];
    #pragma unroll
    for (int i = 1; i < 8; i++) mx = fmaxf(mx, v[i]);
    #pragma unroll
    for (int o = 16; o; o >>= 1) mx = fmaxf(mx, __shfl_xor_sync(0xFFFFFFFFu, mx, o));
    __shared__ float smax[8], ssum[8];
    if ((tid & 31) == 0) smax[tid >> 5] = mx;
    __syncthreads();
    mx = smax[0];
    #pragma unroll
    for (int w = 1; w < 8; w++) mx = fmaxf(mx, smax[w]);

    float sum = 0.0f;
    #pragma unroll
    for (int i = 0; i < 8; i++) { v[i] = __expf(v[i] - mx); sum += v[i]; }
    #pragma unroll
    for (int o = 16; o; o >>= 1) sum += __shfl_xor_sync(0xFFFFFFFFu, sum, o);
    if ((tid & 31) == 0) ssum[tid >> 5] = sum;
    __syncthreads();
    sum = ssum[0];
    #pragma unroll
    for (int w = 1; w < 8; w++) sum += ssum[w];

    float inv = 1.0f / sum;
    uint4 o4;
    o4.x = pack_bf16x2(v[0] * inv, v[1] * inv);
    o4.y = pack_bf16x2(v[2] * inv, v[3] * inv);
    o4.z = pack_bf16x2(v[4] * inv, v[5] * inv);
    o4.w = pack_bf16x2(v[6] * inv, v[7] * inv);
    prow[tid] = o4;
}

// ===========================================================================
extern "C" void kernel_launch(void* const* d_in, const int* in_sizes, int n_in,
                              void* d_out, int out_size)
{
    const float* x  = (const float*)d_in[0];
    const float* Wq = (const float*)d_in[1];
    const float* bq = (const float*)d_in[2];
    const float* Wk = (const float*)d_in[3];
    const float* bk = (const float*)d_in[4];
    const float* Wv = (const float*)d_in[5];
    const float* bv = (const float*)d_in[6];
    float* out = (float*)d_out;

    bf16 *xt, *Wqk, *Wvb, *QK, *Vp, *Sp, *Pp;
    float *bqk;
    cudaGetSymbolAddress((void**)&xt,  g_xt);
    cudaGetSymbolAddress((void**)&Wqk, g_Wqk);
    cudaGetSymbolAddress((void**)&Wvb, g_Wv);
    cudaGetSymbolAddress((void**)&bqk, g_bqk);
    cudaGetSymbolAddress((void**)&QK,  g_QK);
    cudaGetSymbolAddress((void**)&Vp,  g_V);
    cudaGetSymbolAddress((void**)&Sp,  g_S);
    cudaGetSymbolAddress((void**)&Pp,  g_P);

    cudaFuncSetAttribute(mma_gemm<1>, cudaFuncAttributeMaxDynamicSharedMemorySize, SMEMB);
    cudaFuncSetAttribute(mma_gemm<2>, cudaFuncAttributeMaxDynamicSharedMemorySize, SMEMB);
    cudaFuncSetAttribute(mma_gemm<3>, cudaFuncAttributeMaxDynamicSharedMemorySize, SMEMB);
    cudaFuncSetAttribute(mma_gemm<4>, cudaFuncAttributeMaxDynamicSharedMemorySize, SMEMB);

    prep_all<<<513 + 8192, 256>>>(Wq, Wk, Wv, bq, bk, x);

    const size_t sXT = (size_t)N_ * C_;
    const size_t sQK = (size_t)N_ * C_;
    const size_t sX  = (size_t)C_ * N_;
    const size_t sS  = (size_t)N_ * N_;

    // QK[n][o] = sum_c xt[n,c] Wqk[o,c] + bqk[o]   rows=2048, cols=512
    mma_gemm<1><<<dim3(C_ / 128, N_ / 256, B_), 256, SMEMB>>>(
        xt, Wqk, bqk, nullptr, QK, C_, C_, C_, C_, sXT, 0, sQK, 0);
    // V[c][m] = sum_k Wv[c,k] xt[m,k] + bv[c]      rows=512, cols=2048
    mma_gemm<2><<<dim3(N_ / 128, C_ / 256, B_), 256, SMEMB>>>(
        Wvb, xt, bv, nullptr, Vp, C_, C_, C_, N_, 0, sXT, sX, 0);
    // S[n][m] = sum_c Q[n,c] K[m,c]                rows=2048, cols=2048
    mma_gemm<4><<<dim3(N_ / 128, N_ / 256, B_), 256, SMEMB>>>(
        QK, QK + CH_, nullptr, nullptr, Sp, CH_, C_, C_, N_, sQK, sQK, sS, 0);
    // softmax
    softmax_kernel<<<B_ * N_, 256>>>(Sp, Pp);
    // out[c][n] = x[c][n] + sum_m V[c,m] P[n,m]    rows=512, cols=2048
    mma_gemm<3><<<dim3(N_ / 128, C_ / 256, B_), 256, SMEMB>>>(
        Vp, Pp, nullptr, x, out, N_, N_, N_, N_, sX, sS, sX, sX);
}

// round 11
// speedup vs baseline: 1.0679x; 1.0679x over previous
#include <cuda_runtime.h>
#include <cuda_bf16.h>
#include <cstdint>
#include <string.h>
#include <math.h>

typedef __nv_bfloat16 bf16;

#define B_ 8
#define C_ 512
#define N_ 2048
#define CH_ 256

// ---- device-global scratch ----
__device__ bf16  g_xt [B_ * N_ * C_];             // [n][c] bf16
__device__ bf16  g_Wqk[2 * CH_ * C_];             // rows 0-255 Wq, 256-511 Wk
__device__ bf16  g_Wv [C_ * C_];
__device__ float g_bqk[2 * CH_];                  // packed bq|bk
__device__ bf16  g_QK [B_ * N_ * C_];             // [n][0..255]=Q, [256..511]=K
__device__ bf16  g_V  [B_ * C_ * N_];             // [c][m]
__device__ bf16  g_S  [(size_t)B_ * N_ * N_];     // [n][m] unscaled logits, bf16
__device__ bf16  g_P  [(size_t)B_ * N_ * N_];     // [n][m] probs, bf16

// ===========================================================================
// PTX helpers
// ===========================================================================
__device__ __forceinline__ uint32_t smem_u32(const void* p) {
    uint32_t a;
    asm("{ .reg .u64 t; cvta.to.shared.u64 t, %1; cvt.u32.u64 %0, t; }"
        : "=r"(a) : "l"(p));
    return a;
}
__device__ __forceinline__ void cp_async16(uint32_t dst, const void* src) {
    asm volatile("cp.async.cg.shared.global [%0], [%1], 16;\n" :: "r"(dst), "l"(src));
}
__device__ __forceinline__ void cp_commit() {
    asm volatile("cp.async.commit_group;\n");
}
template<int NW> __device__ __forceinline__ void cp_wait() {
    asm volatile("cp.async.wait_group %0;\n" :: "n"(NW));
}
__device__ __forceinline__ void ldsm4(uint32_t* r, uint32_t addr) {
    asm volatile("ldmatrix.sync.aligned.m8n8.x4.shared.b16 {%0,%1,%2,%3}, [%4];\n"
                 : "=r"(r[0]), "=r"(r[1]), "=r"(r[2]), "=r"(r[3]) : "r"(addr));
}
__device__ __forceinline__ void mma16816(float* c, const uint32_t* a,
                                         uint32_t b0, uint32_t b1) {
    asm volatile(
        "mma.sync.aligned.m16n8k16.row.col.f32.bf16.bf16.f32 "
        "{%0,%1,%2,%3}, {%4,%5,%6,%7}, {%8,%9}, {%0,%1,%2,%3};\n"
        : "+f"(c[0]), "+f"(c[1]), "+f"(c[2]), "+f"(c[3])
        : "r"(a[0]), "r"(a[1]), "r"(a[2]), "r"(a[3]), "r"(b0), "r"(b1));
}
__device__ __forceinline__ uint32_t pack_bf16x2(float lo, float hi) {
    __nv_bfloat162 h = __float22bfloat162_rn(make_float2(lo, hi));
    uint32_t u;
    memcpy(&u, &h, 4);
    return u;
}
__device__ __forceinline__ float2 unpack_bf16x2(uint32_t u) {
    __nv_bfloat162 h;
    memcpy(&h, &u, 4);
    return __bfloat1622float2(h);
}

// ===========================================================================
// K-major SS GEMM: D[i,j] = sum_k A[i,k]*B[j,k] + epilogue
// CTA 128x128, 4 warps (2x2), warp tile 64x64, K-chunks of 64, 3-stage
// cp.async pipeline, ONE __syncthreads per stage (wait -> sync -> prefetch).
//   MODE 1: bf16 out + bias[j]
//   MODE 2: bf16 out + bias[i]
//   MODE 3: fp32 out + res[i][j]
//   MODE 4: bf16 out (plain)
// ===========================================================================
#define NSTG 3
#define SMEMB (NSTG * 32768)

template<int MODE>
__global__ void __launch_bounds__(128, 2)
mma_gemm(const bf16* __restrict__ Ag, const bf16* __restrict__ Bg,
         const float* __restrict__ bias, const float* __restrict__ res,
         void* __restrict__ Dg, int Ktot, int lda, int ldb, int ldd,
         size_t sA, size_t sB, size_t sD, size_t sRes)
{
    extern __shared__ char smem[];
    const uint32_t s0 = smem_u32(smem);

    const int tid = threadIdx.x, warp = tid >> 5, lane = tid & 31;
    const int bz = blockIdx.z;
    const int i0 = blockIdx.y * 128, j0 = blockIdx.x * 128;
    const bf16* Ab = Ag + sA * bz;
    const bf16* Bb = Bg + sB * bz;

    const int wm = (warp >> 1) * 64;
    const int wn = (warp & 1) * 64;

    const int rAl = lane & 15;
    const int aHalf = lane >> 4;
    const int rBl = (lane & 7) + ((lane & 16) >> 1);
    const int bHalf = (lane >> 3) & 1;

    float acc[4][8][4];
    #pragma unroll
    for (int mi = 0; mi < 4; mi++)
        #pragma unroll
        for (int ni = 0; ni < 8; ni++)
            #pragma unroll
            for (int e = 0; e < 4; e++) acc[mi][ni][e] = 0.0f;

    auto load_stage = [&](int t) {
        const uint32_t base = s0 + (uint32_t)(t % NSTG) * 32768u;
        const int k0 = t * 64;
        #pragma unroll
        for (int it = 0; it < 16; it++) {
            int q = it * 128 + tid;
            int qq = q & 1023;
            int row = qq >> 3, c = qq & 7;
            uint32_t dst = base + (q < 1024 ? 0u : 16384u)
                         + (uint32_t)(row * 128 + ((c ^ (row & 7)) << 4));
            const bf16* src = (q < 1024)
                ? Ab + (size_t)(i0 + row) * lda + k0 + c * 8
                : Bb + (size_t)(j0 + row) * ldb + k0 + c * 8;
            cp_async16(dst, src);
        }
        cp_commit();
    };

    const int T = Ktot >> 6;
    load_stage(0);
    if (T > 1) load_stage(1);

    for (int t = 0; t < T; t++) {
        // wait for stage t, make it visible, THEN prefetch t+2 (one sync/stage)
        if (t + 1 < T) cp_wait<1>(); else cp_wait<0>();
        __syncthreads();
        if (t + 2 < T) load_stage(t + 2);

        const uint32_t sa = s0 + (uint32_t)(t % NSTG) * 32768u;
        const uint32_t sb = sa + 16384u;
        #pragma unroll
        for (int k16 = 0; k16 < 4; k16++) {
            uint32_t a[4][4], b[4][4];
            #pragma unroll
            for (int mi = 0; mi < 4; mi++) {
                int row = wm + mi * 16 + rAl;
                int ch = 2 * k16 + aHalf;
                ldsm4(a[mi], sa + (uint32_t)(row * 128 + ((ch ^ (row & 7)) << 4)));
            }
            #pragma unroll
            for (int nh = 0; nh < 4; nh++) {
                int row = wn + nh * 16 + rBl;
                int ch = 2 * k16 + bHalf;
                ldsm4(b[nh], sb + (uint32_t)(row * 128 + ((ch ^ (row & 7)) << 4)));
            }
            #pragma unroll
            for (int mi = 0; mi < 4; mi++)
                #pragma unroll
                for (int ni = 0; ni < 8; ni++)
                    mma16816(acc[mi][ni], a[mi],
                             b[ni >> 1][(ni & 1) * 2], b[ni >> 1][(ni & 1) * 2 + 1]);
        }
    }

    // ---- Epilogue ----
    const int er = lane >> 2;
    const int ec = 2 * (lane & 3);
    #pragma unroll
    for (int mi = 0; mi < 4; mi++)
        #pragma unroll
        for (int ni = 0; ni < 8; ni++) {
            const float* a4 = acc[mi][ni];
            int gm = i0 + wm + mi * 16 + er;
            int gn = j0 + wn + ni * 8 + ec;
            if (MODE == 3) {
                float* D = (float*)Dg + sD * bz;
                const float* R = res + sRes * bz;
                float2 r0 = *(const float2*)&R[(size_t)gm * ldd + gn];
                float2 r1 = *(const float2*)&R[(size_t)(gm + 8) * ldd + gn];
                *(float2*)&D[(size_t)gm * ldd + gn] =
                    make_float2(r0.x + a4[0], r0.y + a4[1]);
                *(float2*)&D[(size_t)(gm + 8) * ldd + gn] =
                    make_float2(r1.x + a4[2], r1.y + a4[3]);
            } else if (MODE == 4) {
                bf16* D = (bf16*)Dg + sD * bz;
                *(__nv_bfloat162*)&D[(size_t)gm * ldd + gn] =
                    __float22bfloat162_rn(make_float2(a4[0], a4[1]));
                *(__nv_bfloat162*)&D[(size_t)(gm + 8) * ldd + gn] =
                    __float22bfloat162_rn(make_float2(a4[2], a4[3]));
            } else {
                bf16* D = (bf16*)Dg + sD * bz;
                float b0, b1, b2, b3;
                if (MODE == 1) {
                    b0 = bias[gn]; b1 = bias[gn + 1]; b2 = b0; b3 = b1;
                } else {
                    b0 = b1 = bias[gm]; b2 = b3 = bias[gm + 8];
                }
                *(__nv_bfloat162*)&D[(size_t)gm * ldd + gn] =
                    __float22bfloat162_rn(make_float2(a4[0] + b0, a4[1] + b1));
                *(__nv_bfloat162*)&D[(size_t)(gm + 8) * ldd + gn] =
                    __float22bfloat162_rn(make_float2(a4[2] + b2, a4[3] + b3));
            }
        }
}

// ===========================================================================
// Fused prep: weight conversions + bias pack + x transpose, one launch.
// ===========================================================================
__global__ void __launch_bounds__(256)
prep_all(const float* __restrict__ Wq, const float* __restrict__ Wk,
         const float* __restrict__ Wv, const float* __restrict__ bq,
         const float* __restrict__ bk, const float* __restrict__ x)
{
    __shared__ float tile[32][33];
    const int b = blockIdx.x;
    const int tid = threadIdx.x;

    if (b < 512) {
        const float4* src;
        __nv_bfloat162* dst;
        int idx;
        if (b < 128) {
            src = (const float4*)Wq; dst = (__nv_bfloat162*)g_Wqk;
            idx = b * 256 + tid;
        } else if (b < 256) {
            src = (const float4*)Wk; dst = (__nv_bfloat162*)(g_Wqk + CH_ * C_);
            idx = (b - 128) * 256 + tid;
        } else {
            src = (const float4*)Wv; dst = (__nv_bfloat162*)g_Wv;
            idx = (b - 256) * 256 + tid;
        }
        float4 v = src[idx];
        dst[2 * idx]     = __float22bfloat162_rn(make_float2(v.x, v.y));
        dst[2 * idx + 1] = __float22bfloat162_rn(make_float2(v.z, v.w));
        if (b >= 256) {
            int idx2 = idx + 256 * 128;
            float4 v2 = ((const float4*)Wv)[idx2];
            dst[2 * idx2]     = __float22bfloat162_rn(make_float2(v2.x, v2.y));
            dst[2 * idx2 + 1] = __float22bfloat162_rn(make_float2(v2.z, v2.w));
        }
    } else if (b == 512) {
        g_bqk[tid]        = bq[tid];
        g_bqk[tid + CH_]  = bk[tid];
    } else {
        int t = b - 513;
        int bx = t & 63;
        int by = (t >> 6) & 15;
        int bz = t >> 10;
        const int c0 = by * 32, n0 = bx * 32;
        const float* xb = x + (size_t)bz * C_ * N_;
        bf16* xtb = g_xt + (size_t)bz * N_ * C_;
        const int tx = tid & 31, ty = tid >> 5;
        #pragma unroll
        for (int i = 0; i < 4; i++)
            tile[ty + 8 * i][tx] = xb[(size_t)(c0 + ty + 8 * i) * N_ + n0 + tx];
        __syncthreads();
        #pragma unroll
        for (int i = 0; i < 4; i++)
            xtb[(size_t)(n0 + ty + 8 * i) * C_ + c0 + tx] =
                __float2bfloat16(tile[tx][ty + 8 * i]);
    }
}

// ===========================================================================
// Softmax over last dim (2048). bf16 in (x1/16 at load), bf16 out.
// ===========================================================================
__global__ void __launch_bounds__(256)
softmax_kernel(const bf16* __restrict__ S, bf16* __restrict__ P)
{
    const uint4* row = (const uint4*)(S + (size_t)blockIdx.x * N_);
    uint4* prow = (uint4*)(P + (size_t)blockIdx.x * N_);
    const int tid = threadIdx.x;

    uint4 u = row[tid];
    float v[8];
    {
        float2 f;
        f = unpack_bf16x2(u.x); v[0] = f.x * 0.0625f; v[1] = f.y * 0.0625f;
        f = unpack_bf16x2(u.y); v[2] = f.x * 0.0625f; v[3] = f.y * 0.0625f;
        f = unpack_bf16x2(u.z); v[4] = f.x * 0.0625f; v[5] = f.y * 0.0625f;
        f = unpack_bf16x2(u.w); v[6] = f.x * 0.0625f; v[7] = f.y * 0.0625f;
    }
    float mx = v[0];
    #pragma unroll
    for (int i = 1; i < 8; i++) mx = fmaxf(mx, v[i]);
    #pragma unroll
    for (int o = 16; o; o >>= 1) mx = fmaxf(mx, __shfl_xor_sync(0xFFFFFFFFu, mx, o));
    __shared__ float smax[8], ssum[8];
    if ((tid & 31) == 0) smax[tid >> 5] = mx;
    __syncthreads();
    mx = smax[0];
    #pragma unroll
    for (int w = 1; w < 8; w++) mx = fmaxf(mx, smax[w]);

    float sum = 0.0f;
    #pragma unroll
    for (int i = 0; i < 8; i++) { v[i] = __expf(v[i] - mx); sum += v[i]; }
    #pragma unroll
    for (int o = 16; o; o >>= 1) sum += __shfl_xor_sync(0xFFFFFFFFu, sum, o);
    if ((tid & 31) == 0) ssum[tid >> 5] = sum;
    __syncthreads();
    sum = ssum[0];
    #pragma unroll
    for (int w = 1; w < 8; w++) sum += ssum[w];

    float inv = 1.0f / sum;
    uint4 o4;
    o4.x = pack_bf16x2(v[0] * inv, v[1] * inv);
    o4.y = pack_bf16x2(v[2] * inv, v[3] * inv);
    o4.z = pack_bf16x2(v[4] * inv, v[5] * inv);
    o4.w = pack_bf16x2(v[6] * inv, v[7] * inv);
    prow[tid] = o4;
}

// ===========================================================================
extern "C" void kernel_launch(void* const* d_in, const int* in_sizes, int n_in,
                              void* d_out, int out_size)
{
    const float* x  = (const float*)d_in[0];
    const float* Wq = (const float*)d_in[1];
    const float* bq = (const float*)d_in[2];
    const float* Wk = (const float*)d_in[3];
    const float* bk = (const float*)d_in[4];
    const float* Wv = (const float*)d_in[5];
    const float* bv = (const float*)d_in[6];
    float* out = (float*)d_out;

    bf16 *xt, *Wqk, *Wvb, *QK, *Vp, *Sp, *Pp;
    float *bqk;
    cudaGetSymbolAddress((void**)&xt,  g_xt);
    cudaGetSymbolAddress((void**)&Wqk, g_Wqk);
    cudaGetSymbolAddress((void**)&Wvb, g_Wv);
    cudaGetSymbolAddress((void**)&bqk, g_bqk);
    cudaGetSymbolAddress((void**)&QK,  g_QK);
    cudaGetSymbolAddress((void**)&Vp,  g_V);
    cudaGetSymbolAddress((void**)&Sp,  g_S);
    cudaGetSymbolAddress((void**)&Pp,  g_P);

    cudaFuncSetAttribute(mma_gemm<1>, cudaFuncAttributeMaxDynamicSharedMemorySize, SMEMB);
    cudaFuncSetAttribute(mma_gemm<2>, cudaFuncAttributeMaxDynamicSharedMemorySize, SMEMB);
    cudaFuncSetAttribute(mma_gemm<3>, cudaFuncAttributeMaxDynamicSharedMemorySize, SMEMB);
    cudaFuncSetAttribute(mma_gemm<4>, cudaFuncAttributeMaxDynamicSharedMemorySize, SMEMB);

    prep_all<<<513 + 8192, 256>>>(Wq, Wk, Wv, bq, bk, x);

    const size_t sXT = (size_t)N_ * C_;
    const size_t sQK = (size_t)N_ * C_;
    const size_t sX  = (size_t)C_ * N_;
    const size_t sS  = (size_t)N_ * N_;

    // QK[n][o] = sum_c xt[n,c] Wqk[o,c] + bqk[o]
    mma_gemm<1><<<dim3(C_ / 128, N_ / 128, B_), 128, SMEMB>>>(
        xt, Wqk, bqk, nullptr, QK, C_, C_, C_, C_, sXT, 0, sQK, 0);
    // V[c][m] = sum_k Wv[c,k] xt[m,k] + bv[c]
    mma_gemm<2><<<dim3(N_ / 128, C_ / 128, B_), 128, SMEMB>>>(
        Wvb, xt, bv, nullptr, Vp, C_, C_, C_, N_, 0, sXT, sX, 0);
    // S[n][m] = sum_c Q[n,c] K[m,c]   (unscaled, bf16 out)
    mma_gemm<4><<<dim3(N_ / 128, N_ / 128, B_), 128, SMEMB>>>(
        QK, QK + CH_, nullptr, nullptr, Sp, CH_, C_, C_, N_, sQK, sQK, sS, 0);
    // softmax (applies 1/16 at load)
    softmax_kernel<<<B_ * N_, 256>>>(Sp, Pp);
    // out[c][n] = x[c][n] + sum_m V[c,m] P[n,m]
    mma_gemm<3><<<dim3(N_ / 128, C_ / 128, B_), 128, SMEMB>>>(
        Vp, Pp, nullptr, x, out, N_, N_, N_, N_, sX, sS, sX, sX);
}